// round 10
// baseline (speedup 1.0000x reference)
#include <cuda_runtime.h>
#include <cstdint>

#define B_ 8
#define C_ 256
#define D_ 64
#define N_ 2048
#define M_ 2048

typedef unsigned long long ull;

__device__ float g_q[B_ * C_ * N_];
__device__ float g_k[B_ * C_ * M_];
__device__ float g_v[B_ * C_ * M_];
__device__ float g_attn[B_ * C_ * N_];
__device__ float g_h[B_ * 2 * C_ * N_];
__device__ float g_bias1[2 * C_];
__device__ float g_inv[2 * C_];
__device__ float g_Wcomb[2 * C_ * 2 * C_];   // [512][512]: [Wc1a | Wc1b@Wm]

// ---------------- packed f32x2 primitives ---------------------------------------
__device__ __forceinline__ ull ffma2(ull a, ull b, ull c) {
    ull d; asm("fma.rn.f32x2 %0,%1,%2,%3;" : "=l"(d) : "l"(a), "l"(b), "l"(c)); return d;
}
__device__ __forceinline__ ull fadd2(ull a, ull b) {
    ull d; asm("add.rn.f32x2 %0,%1,%2;" : "=l"(d) : "l"(a), "l"(b)); return d;
}
__device__ __forceinline__ ull fsub2(ull a, ull b) {
    ull d; asm("sub.rn.f32x2 %0,%1,%2;" : "=l"(d) : "l"(a), "l"(b)); return d;
}
__device__ __forceinline__ ull fmul2(ull a, ull b) {
    ull d; asm("mul.rn.f32x2 %0,%1,%2;" : "=l"(d) : "l"(a), "l"(b)); return d;
}
__device__ __forceinline__ ull pack2(float x) {
    ull d; asm("mov.b64 %0,{%1,%1};" : "=l"(d) : "f"(x)); return d;
}
__device__ __forceinline__ void unpack2(ull v, float& lo, float& hi) {
    asm("mov.b64 {%0,%1},%2;" : "=f"(lo), "=f"(hi) : "l"(v));
}
__device__ __forceinline__ void unpack2u(ull v, uint32_t& lo, uint32_t& hi) {
    asm("mov.b64 {%0,%1},%2;" : "=r"(lo), "=r"(hi) : "l"(v));
}
__device__ __forceinline__ ull pack2u(uint32_t lo, uint32_t hi) {
    ull d; asm("mov.b64 %0,{%1,%2};" : "=l"(d) : "r"(lo), "r"(hi)); return d;
}
__device__ __forceinline__ ull d2u(double x) { return __double_as_longlong(x); }

struct ExpC { ull c5, c4, c3, c2, c1, c0, mag, nmag; };
__device__ __forceinline__ ull exp2pk(ull t2, const ExpC& E) {
    ull r2 = fadd2(t2, E.mag);
    ull g2 = fadd2(r2, E.nmag);
    ull f2 = fsub2(t2, g2);
    ull p2 = ffma2(E.c5, f2, E.c4);
    p2 = ffma2(p2, f2, E.c3);
    p2 = ffma2(p2, f2, E.c2);
    p2 = ffma2(p2, f2, E.c1);
    p2 = ffma2(p2, f2, E.c0);
    uint32_t ilo, ihi;
    unpack2u(r2, ilo, ihi);
    uint32_t slo = (ilo + (127u - 0x400000u)) << 23;
    uint32_t shi = (ihi + (127u - 0x400000u)) << 23;
    return fmul2(p2, pack2u(slo, shi));
}

// ---------------- fold: BN + Wc1b@bm into bias1; copy Wc1a into g_Wcomb ----------
__global__ void fold_kernel(const float* __restrict__ Wc1, const float* __restrict__ bc1,
                            const float* __restrict__ bm,
                            const float* __restrict__ gamma, const float* __restrict__ beta,
                            const float* __restrict__ mean, const float* __restrict__ var) {
    int o = blockIdx.x * blockDim.x + threadIdx.x;
    if (o >= 2 * C_) return;
    float inv = gamma[o] * rsqrtf(var[o] + 1e-5f);
    g_inv[o] = inv;
    float s = 0.0f;
    const float* wrow = Wc1 + (size_t)o * (2 * C_) + C_;
#pragma unroll 4
    for (int j = 0; j < C_; j++) s = fmaf(wrow[j], bm[j], s);
    g_bias1[o] = inv * (bc1[o] + s - mean[o]) + beta[o];
}

__global__ void combcopy_kernel(const float* __restrict__ Wc1) {
    const int o = blockIdx.x;
    const int t = threadIdx.x;
    g_Wcomb[(size_t)o * (2 * C_) + t] = Wc1[(size_t)o * (2 * C_) + t];
}

// ---------------- fused QKV GEMM ---------------------------------------------------
__global__ void __launch_bounds__(256, 2) qkv_gemm(
    const float* __restrict__ desc1, const float* __restrict__ desc2,
    const float* __restrict__ Wq, const float* __restrict__ bq,
    const float* __restrict__ Wk, const float* __restrict__ bk,
    const float* __restrict__ Wv, const float* __restrict__ bv,
    const float* __restrict__ weight_v,
    float* __restrict__ Yq, float* __restrict__ Yk, float* __restrict__ Yv,
    float qscale) {
    __shared__ ull   sW2[2][16][128];
    __shared__ float sX[2][16][128];
    const int tid = threadIdx.x;
    const int tx = tid & 15, ty = tid >> 4;
    const int n0 = blockIdx.x * 128;
    const int sel = blockIdx.y >> 1;
    const int o0 = (blockIdx.y & 1) * 128;
    const int bz = blockIdx.z;

    const float* W = (sel == 0) ? Wq : (sel == 1) ? Wk : Wv;
    const float* bias = (sel == 0) ? bq : (sel == 1) ? bk : bv;
    const float* X = (sel == 0) ? desc1 : desc2;
    float* Y = (sel == 0) ? Yq : (sel == 1) ? Yk : Yv;
    const float outscale = (sel == 0) ? qscale : 1.0f;
    const float* colscale = (sel == 2) ? (weight_v + (size_t)bz * M_) : nullptr;
    const float* Xb = X + (size_t)bz * ((long long)C_ * N_);

    const int wr = tid >> 1;
    const int wc = (tid & 1) * 8;
    const float* Wp = W + (size_t)(o0 + wr) * C_ + wc;
    const int xr0 = tid >> 5;
    const int xc0 = (tid & 31) * 4;

    float wbuf[8]; float4 xbuf[2];
    {
        const float4 a = *(const float4*)(Wp);
        const float4 b = *(const float4*)(Wp + 4);
        wbuf[0] = a.x; wbuf[1] = a.y; wbuf[2] = a.z; wbuf[3] = a.w;
        wbuf[4] = b.x; wbuf[5] = b.y; wbuf[6] = b.z; wbuf[7] = b.w;
#pragma unroll
        for (int l = 0; l < 2; l++)
            xbuf[l] = *(const float4*)(Xb + (size_t)(xr0 + l * 8) * N_ + n0 + xc0);
#pragma unroll
        for (int i = 0; i < 8; i++) sW2[0][wc + i][wr] = pack2(wbuf[i]);
#pragma unroll
        for (int l = 0; l < 2; l++) *(float4*)&sX[0][xr0 + l * 8][xc0] = xbuf[l];
    }
    __syncthreads();

    ull acc[8][4];
#pragma unroll
    for (int a = 0; a < 8; a++)
#pragma unroll
        for (int j = 0; j < 4; j++) acc[a][j] = 0ull;

    int buf = 0;
    for (int blk = 0; blk < 16; blk++) {
        const bool more = (blk + 1 < 16);
        if (more) {
            const int kk = (blk + 1) << 4;
            const float4 a = *(const float4*)(Wp + kk);
            const float4 b = *(const float4*)(Wp + kk + 4);
            wbuf[0] = a.x; wbuf[1] = a.y; wbuf[2] = a.z; wbuf[3] = a.w;
            wbuf[4] = b.x; wbuf[5] = b.y; wbuf[6] = b.z; wbuf[7] = b.w;
#pragma unroll
            for (int l = 0; l < 2; l++)
                xbuf[l] = *(const float4*)(Xb + (size_t)(kk + xr0 + l * 8) * N_ + n0 + xc0);
        }
#pragma unroll
        for (int k = 0; k < 16; k++) {
            const ulonglong2 wA = *(const ulonglong2*)&sW2[buf][k][ty * 8];
            const ulonglong2 wB = *(const ulonglong2*)&sW2[buf][k][ty * 8 + 2];
            const ulonglong2 wC = *(const ulonglong2*)&sW2[buf][k][ty * 8 + 4];
            const ulonglong2 wD = *(const ulonglong2*)&sW2[buf][k][ty * 8 + 6];
            const double2 xa = *(const double2*)&sX[buf][k][tx * 4];
            const double2 xb = *(const double2*)&sX[buf][k][64 + tx * 4];
            const ull x4[4] = {d2u(xa.x), d2u(xa.y), d2u(xb.x), d2u(xb.y)};
            const ull wv2[8] = {wA.x, wA.y, wB.x, wB.y, wC.x, wC.y, wD.x, wD.y};
#pragma unroll
            for (int a = 0; a < 8; a++)
#pragma unroll
                for (int j = 0; j < 4; j++) acc[a][j] = ffma2(wv2[a], x4[j], acc[a][j]);
        }
        if (more) {
#pragma unroll
            for (int i = 0; i < 8; i++) sW2[buf ^ 1][wc + i][wr] = pack2(wbuf[i]);
#pragma unroll
            for (int l = 0; l < 2; l++) *(float4*)&sX[buf ^ 1][xr0 + l * 8][xc0] = xbuf[l];
        }
        __syncthreads();
        buf ^= 1;
    }

    const int nA = n0 + tx * 4, nB = n0 + 64 + tx * 4;
    float cs[8];
#pragma unroll
    for (int j = 0; j < 8; j++) cs[j] = 1.0f;
    if (colscale) {
        const float4 ca = *(const float4*)(colscale + nA);
        const float4 cb = *(const float4*)(colscale + nB);
        cs[0] = ca.x; cs[1] = ca.y; cs[2] = ca.z; cs[3] = ca.w;
        cs[4] = cb.x; cs[5] = cb.y; cs[6] = cb.z; cs[7] = cb.w;
    }
#pragma unroll
    for (int a = 0; a < 8; a++) {
        const int o = o0 + ty * 8 + a;
        float t[8];
        unpack2(acc[a][0], t[0], t[1]);
        unpack2(acc[a][1], t[2], t[3]);
        unpack2(acc[a][2], t[4], t[5]);
        unpack2(acc[a][3], t[6], t[7]);
        const float bo = bias[o];
#pragma unroll
        for (int j = 0; j < 8; j++) t[j] = (t[j] + bo) * outscale * cs[j];
        float* yp = Y + (size_t)bz * ((long long)C_ * N_) + (size_t)o * N_;
        float4 oa4, ob4;
        oa4.x = t[0]; oa4.y = t[1]; oa4.z = t[2]; oa4.w = t[3];
        ob4.x = t[4]; ob4.y = t[5]; ob4.z = t[6]; ob4.w = t[7];
        *(float4*)(yp + nA) = oa4;
        *(float4*)(yp + nB) = ob4;
    }
}

// ---------------- GEMM v4 + ldY ---------------------------------------------------
__global__ void __launch_bounds__(256, 2) gemm4(
    const float* __restrict__ W, int ldW,
    const float* __restrict__ X0, long long xbs0,
    const float* __restrict__ X1, long long xbs1, int K0,
    int CIN, int L,
    float* __restrict__ Y, long long ybs, int ldY,
    const float* __restrict__ bias,
    const float* __restrict__ rowscale,
    const float* __restrict__ resid, long long rbs,
    float outscale, int relu) {
    __shared__ ull   sW2[2][16][128];
    __shared__ float sX[2][16][128];
    const int tid = threadIdx.x;
    const int tx = tid & 15, ty = tid >> 4;
    const int n0 = blockIdx.x * 128, o0 = blockIdx.y * 128;
    const int bz = blockIdx.z;

    const int wr = tid >> 1;
    const int wc = (tid & 1) * 8;
    const float* Wp = W + (size_t)(o0 + wr) * ldW + wc;
    const int xr0 = tid >> 5;
    const int xc0 = (tid & 31) * 4;

    float wbuf[8]; float4 xbuf[2];
    {
        const float4 a = *(const float4*)(Wp);
        const float4 b = *(const float4*)(Wp + 4);
        wbuf[0] = a.x; wbuf[1] = a.y; wbuf[2] = a.z; wbuf[3] = a.w;
        wbuf[4] = b.x; wbuf[5] = b.y; wbuf[6] = b.z; wbuf[7] = b.w;
#pragma unroll
        for (int l = 0; l < 2; l++) {
            const int k = xr0 + l * 8;
            const float* xs = (k < K0)
                ? X0 + (size_t)bz * xbs0 + (size_t)k * L
                : X1 + (size_t)bz * xbs1 + (size_t)(k - K0) * L;
            xbuf[l] = *(const float4*)(xs + n0 + xc0);
        }
#pragma unroll
        for (int i = 0; i < 8; i++) sW2[0][wc + i][wr] = pack2(wbuf[i]);
#pragma unroll
        for (int l = 0; l < 2; l++) *(float4*)&sX[0][xr0 + l * 8][xc0] = xbuf[l];
    }
    __syncthreads();

    ull acc[8][4];
#pragma unroll
    for (int a = 0; a < 8; a++)
#pragma unroll
        for (int j = 0; j < 4; j++) acc[a][j] = 0ull;

    const int nblk = CIN >> 4;
    int buf = 0;
    for (int blk = 0; blk < nblk; blk++) {
        const bool more = (blk + 1 < nblk);
        if (more) {
            const int kk = (blk + 1) << 4;
            const float4 a = *(const float4*)(Wp + kk);
            const float4 b = *(const float4*)(Wp + kk + 4);
            wbuf[0] = a.x; wbuf[1] = a.y; wbuf[2] = a.z; wbuf[3] = a.w;
            wbuf[4] = b.x; wbuf[5] = b.y; wbuf[6] = b.z; wbuf[7] = b.w;
#pragma unroll
            for (int l = 0; l < 2; l++) {
                const int k = kk + xr0 + l * 8;
                const float* xs = (k < K0)
                    ? X0 + (size_t)bz * xbs0 + (size_t)k * L
                    : X1 + (size_t)bz * xbs1 + (size_t)(k - K0) * L;
                xbuf[l] = *(const float4*)(xs + n0 + xc0);
            }
        }
#pragma unroll
        for (int k = 0; k < 16; k++) {
            const ulonglong2 wA = *(const ulonglong2*)&sW2[buf][k][ty * 8];
            const ulonglong2 wB = *(const ulonglong2*)&sW2[buf][k][ty * 8 + 2];
            const ulonglong2 wC = *(const ulonglong2*)&sW2[buf][k][ty * 8 + 4];
            const ulonglong2 wD = *(const ulonglong2*)&sW2[buf][k][ty * 8 + 6];
            const double2 xa = *(const double2*)&sX[buf][k][tx * 4];
            const double2 xb = *(const double2*)&sX[buf][k][64 + tx * 4];
            const ull x4[4] = {d2u(xa.x), d2u(xa.y), d2u(xb.x), d2u(xb.y)};
            const ull wv2[8] = {wA.x, wA.y, wB.x, wB.y, wC.x, wC.y, wD.x, wD.y};
#pragma unroll
            for (int a = 0; a < 8; a++)
#pragma unroll
                for (int j = 0; j < 4; j++) acc[a][j] = ffma2(wv2[a], x4[j], acc[a][j]);
        }
        if (more) {
#pragma unroll
            for (int i = 0; i < 8; i++) sW2[buf ^ 1][wc + i][wr] = pack2(wbuf[i]);
#pragma unroll
            for (int l = 0; l < 2; l++) *(float4*)&sX[buf ^ 1][xr0 + l * 8][xc0] = xbuf[l];
        }
        __syncthreads();
        buf ^= 1;
    }

    const int nA = n0 + tx * 4, nB = n0 + 64 + tx * 4;
#pragma unroll
    for (int a = 0; a < 8; a++) {
        const int o = o0 + ty * 8 + a;
        float t[8];
        unpack2(acc[a][0], t[0], t[1]);
        unpack2(acc[a][1], t[2], t[3]);
        unpack2(acc[a][2], t[4], t[5]);
        unpack2(acc[a][3], t[6], t[7]);
        const float rs = rowscale ? rowscale[o] : 1.0f;
        const float bo = bias ? bias[o] : 0.0f;
#pragma unroll
        for (int j = 0; j < 8; j++) t[j] = fmaf(t[j], rs, bo) * outscale;
        if (relu) {
#pragma unroll
            for (int j = 0; j < 8; j++) t[j] = fmaxf(t[j], 0.0f);
        }
        if (resid) {
            const float4 ra = *(const float4*)(resid + (size_t)bz * rbs + (size_t)o * ldY + nA);
            const float4 rb = *(const float4*)(resid + (size_t)bz * rbs + (size_t)o * ldY + nB);
            t[0] += ra.x; t[1] += ra.y; t[2] += ra.z; t[3] += ra.w;
            t[4] += rb.x; t[5] += rb.y; t[6] += rb.z; t[7] += rb.w;
        }
        float4 oa4, ob4;
        oa4.x = t[0]; oa4.y = t[1]; oa4.z = t[2]; oa4.w = t[3];
        ob4.x = t[4]; ob4.y = t[5]; ob4.z = t[6]; ob4.w = t[7];
        *(float4*)(Y + (size_t)bz * ybs + (size_t)o * ldY + nA) = oa4;
        *(float4*)(Y + (size_t)bz * ybs + (size_t)o * ldY + nB) = ob4;
    }
}

// ---------------- flash128b: n-paired S registers ---------------------------------
#define F_SQ 0
#define F_SK (64 * 128)
#define F_SV (F_SK + 64 * 68)
#define F_SPT (F_SV + 64 * 68)
#define F_SL (F_SPT + 64 * 130)
#define F_SMEM_FLOATS (F_SL + 128)
#define F_SMEM_BYTES (F_SMEM_FLOATS * 4)

__global__ void __launch_bounds__(256, 2) flash128b_kernel() {
    extern __shared__ float sm[];
    float* sQ = sm + F_SQ;      // [64][128] d-major
    float* sK = sm + F_SK;      // [64][68]
    float* sV = sm + F_SV;      // [64][68]
    float* sPT = sm + F_SPT;    // [64][130] m rows, n cols
    float* sL = sm + F_SL;      // [128]

    const int tid = threadIdx.x;
    const int tx = tid & 15, ty = tid >> 4;
    const int b = blockIdx.y >> 2, h = blockIdx.y & 3;
    const size_t base = ((size_t)b * C_ + h * D_) * (size_t)N_;
    const float* qg = g_q + base + blockIdx.x * 128;
    const float* kg = g_k + base;
    const float* vg = g_v + base;
    float* og = g_attn + base + blockIdx.x * 128;

    ExpC E;
    E.c5 = pack2(1.3333558e-3f); E.c4 = pack2(9.6181291e-3f);
    E.c3 = pack2(5.5504109e-2f); E.c2 = pack2(2.4022651e-1f);
    E.c1 = pack2(6.9314718e-1f); E.c0 = pack2(1.0f);
    E.mag = pack2(12582912.0f);  E.nmag = pack2(-12582912.0f);

#pragma unroll
    for (int l = 0; l < 8; l++) {
        const int idx = tid + l * 256;
        const int r = idx >> 5, c4 = idx & 31;
        *(float4*)&sQ[r * 128 + c4 * 4] = *(const float4*)(qg + (size_t)r * N_ + c4 * 4);
    }

    // n-pair bases for this thread (S/exp phases): 4ty, 4ty+2, 64+4ty, 64+4ty+2
    ull oa2[4][4];      // O phase: [d=4ty+a][n-pairs 4tx,4tx+2,64+4tx,64+4tx+2]
    ull lsum2[4];       // l partial sums, paired along n
#pragma unroll
    for (int a = 0; a < 4; a++)
#pragma unroll
        for (int j = 0; j < 4; j++) oa2[a][j] = 0ull;
#pragma unroll
    for (int i = 0; i < 4; i++) lsum2[i] = 0ull;
    __syncthreads();

    const int stag = tx >> 2;

    for (int mt = 0; mt < M_; mt += 64) {
#pragma unroll
        for (int l = 0; l < 4; l++) {
            const int idx = tid + l * 256;
            const int r = idx >> 4, c = (idx & 15) << 2;
            *(float4*)&sK[r * 68 + c] = *(const float4*)(kg + (size_t)r * M_ + mt + c);
            *(float4*)&sV[r * 68 + c] = *(const float4*)(vg + (size_t)r * M_ + mt + c);
        }
        __syncthreads();

        // S[np][mm]: np pairs n={nb,nb+1}, nb in {4ty,4ty+2,64+4ty,64+4ty+2}; m=4tx+mm
        ull s2[4][4];
#pragma unroll
        for (int i = 0; i < 4; i++)
#pragma unroll
            for (int j = 0; j < 4; j++) s2[i][j] = 0ull;
#pragma unroll 4
        for (int d = 0; d < 64; d++) {
            const ulonglong2 qA = *(const ulonglong2*)&sQ[d * 128 + (ty << 2)];
            const ulonglong2 qB = *(const ulonglong2*)&sQ[d * 128 + 64 + (ty << 2)];
            const ull qp[4] = {qA.x, qA.y, qB.x, qB.y};
            const float4 kf = *(const float4*)&sK[d * 68 + (tx << 2)];
            const float kfa[4] = {kf.x, kf.y, kf.z, kf.w};
#pragma unroll
            for (int mm = 0; mm < 4; mm++) {
                const ull kp = pack2(kfa[mm]);
#pragma unroll
                for (int np = 0; np < 4; np++)
                    s2[np][mm] = ffma2(qp[np], kp, s2[np][mm]);
            }
        }

        // exp in place, accumulate l, store paired P^T (STS64, staggered over mm)
#pragma unroll
        for (int np = 0; np < 4; np++) {
#pragma unroll
            for (int mm = 0; mm < 4; mm++) {
                s2[np][mm] = exp2pk(s2[np][mm], E);
                lsum2[np] = fadd2(lsum2[np], s2[np][mm]);
            }
            const int nb = ((np >> 1) * 64) + (ty << 2) + ((np & 1) << 1);
#pragma unroll
            for (int jl = 0; jl < 4; jl++) {
                const int jj = (jl + stag) & 3;
                *(ull*)&sPT[((tx << 2) + jj) * 130 + nb] = s2[np][jj];
            }
        }
        __syncthreads();

        // O[4d][8n] += V[d][m] * P[n][m]
#pragma unroll 2
        for (int mb = 0; mb < 64; mb += 4) {
            float4 vv4[4];
#pragma unroll
            for (int a = 0; a < 4; a++)
                vv4[a] = *(const float4*)&sV[((ty << 2) + a) * 68 + mb];
            const float* vvf = (const float*)vv4;
#pragma unroll
            for (int mm = 0; mm < 4; mm++) {
                const float* ptrow = &sPT[(mb + mm) * 130];
                const ull p0 = *(const ull*)&ptrow[(tx << 2)];
                const ull p1 = *(const ull*)&ptrow[(tx << 2) + 2];
                const ull p2 = *(const ull*)&ptrow[64 + (tx << 2)];
                const ull p3 = *(const ull*)&ptrow[64 + (tx << 2) + 2];
#pragma unroll
                for (int a = 0; a < 4; a++) {
                    const ull vb = pack2(vvf[a * 4 + mm]);
                    oa2[a][0] = ffma2(vb, p0, oa2[a][0]);
                    oa2[a][1] = ffma2(vb, p1, oa2[a][1]);
                    oa2[a][2] = ffma2(vb, p2, oa2[a][2]);
                    oa2[a][3] = ffma2(vb, p3, oa2[a][3]);
                }
            }
        }
        __syncthreads();
    }

    // l reduce over tx (each pair lane is a distinct n)
#pragma unroll
    for (int np = 0; np < 4; np++) {
        float lo, hi;
        unpack2(lsum2[np], lo, hi);
        lo += __shfl_xor_sync(0xffffffffu, lo, 1);
        hi += __shfl_xor_sync(0xffffffffu, hi, 1);
        lo += __shfl_xor_sync(0xffffffffu, lo, 2);
        hi += __shfl_xor_sync(0xffffffffu, hi, 2);
        lo += __shfl_xor_sync(0xffffffffu, lo, 4);
        hi += __shfl_xor_sync(0xffffffffu, hi, 4);
        lo += __shfl_xor_sync(0xffffffffu, lo, 8);
        hi += __shfl_xor_sync(0xffffffffu, hi, 8);
        if (tx == 0) {
            const int nb = ((np >> 1) * 64) + (ty << 2) + ((np & 1) << 1);
            sL[nb] = lo; sL[nb + 1] = hi;
        }
    }
    __syncthreads();
    float li[8];
#pragma unroll
    for (int j = 0; j < 4; j++) {
        li[j] = 1.0f / sL[(tx << 2) + j];
        li[4 + j] = 1.0f / sL[64 + (tx << 2) + j];
    }
#pragma unroll
    for (int a = 0; a < 4; a++) {
        const int dd = (ty << 2) + a;
        float t[8];
        unpack2(oa2[a][0], t[0], t[1]);
        unpack2(oa2[a][1], t[2], t[3]);
        unpack2(oa2[a][2], t[4], t[5]);
        unpack2(oa2[a][3], t[6], t[7]);
        float4 o4a, o4b;
        o4a.x = t[0] * li[0]; o4a.y = t[1] * li[1];
        o4a.z = t[2] * li[2]; o4a.w = t[3] * li[3];
        o4b.x = t[4] * li[4]; o4b.y = t[5] * li[5];
        o4b.z = t[6] * li[6]; o4b.w = t[7] * li[7];
        *(float4*)(og + (size_t)dd * N_ + (tx << 2)) = o4a;
        *(float4*)(og + (size_t)dd * N_ + 64 + (tx << 2)) = o4b;
    }
}

// ---------------- launcher -------------------------------------------------------
extern "C" void kernel_launch(void* const* d_in, const int* in_sizes, int n_in,
                              void* d_out, int out_size) {
    const float* desc1 = (const float*)d_in[0];
    const float* desc2 = (const float*)d_in[1];
    const float* weight_v = (const float*)d_in[2];
    const float* Wq = (const float*)d_in[3];
    const float* bq = (const float*)d_in[4];
    const float* Wk = (const float*)d_in[5];
    const float* bk = (const float*)d_in[6];
    const float* Wv = (const float*)d_in[7];
    const float* bv = (const float*)d_in[8];
    const float* Wm = (const float*)d_in[9];
    const float* bm = (const float*)d_in[10];
    const float* Wc1 = (const float*)d_in[11];
    const float* bc1 = (const float*)d_in[12];
    const float* gamma = (const float*)d_in[13];
    const float* beta  = (const float*)d_in[14];
    const float* mean  = (const float*)d_in[15];
    const float* var   = (const float*)d_in[16];
    const float* Wc2 = (const float*)d_in[17];
    const float* bc2 = (const float*)d_in[18];
    float* out = (float*)d_out;

    float *q, *k, *v, *attn, *h, *bias1, *inv, *wcomb;
    cudaGetSymbolAddress((void**)&q, g_q);
    cudaGetSymbolAddress((void**)&k, g_k);
    cudaGetSymbolAddress((void**)&v, g_v);
    cudaGetSymbolAddress((void**)&attn, g_attn);
    cudaGetSymbolAddress((void**)&h, g_h);
    cudaGetSymbolAddress((void**)&bias1, g_bias1);
    cudaGetSymbolAddress((void**)&inv, g_inv);
    cudaGetSymbolAddress((void**)&wcomb, g_Wcomb);

    cudaFuncSetAttribute(flash128b_kernel, cudaFuncAttributeMaxDynamicSharedMemorySize, F_SMEM_BYTES);

    const long long PB = (long long)C_ * N_;
    const long long PB2 = (long long)2 * C_ * N_;

    const float QSCALE = 0.125f * 1.4426950408889634f;

    // weight preprocessing: bias1 (BN + Wc1b@bm), Wcomb = [Wc1a | Wc1b@Wm]
    fold_kernel<<<2, 256>>>(Wc1, bc1, bm, gamma, beta, mean, var);
    combcopy_kernel<<<512, 256>>>(Wc1);
    gemm4<<<dim3(2, 4, 1), 256>>>(Wc1 + C_, 2 * C_, Wm, 0, Wm, 0, C_, C_, C_,
                                  wcomb + C_, 0, 2 * C_,
                                  nullptr, nullptr, nullptr, 0, 1.0f, 0);

    // fused q,k,v projections
    qkv_gemm<<<dim3(N_ / 128, 6, B_), 256>>>(desc1, desc2, Wq, bq, Wk, bk, Wv, bv,
                                             weight_v, q, k, v, QSCALE);
    // attention
    flash128b_kernel<<<dim3(N_ / 128, B_ * 4), 256, F_SMEM_BYTES>>>();
    // h = relu( inv * (Wcomb @ [desc1; attn]) + bias1 )   (Wm GEMM folded away)
    gemm4<<<dim3(16, 4, B_), 256>>>(wcomb, 2 * C_, desc1, PB, attn, PB, C_, 2 * C_, N_,
                                    h, PB2, N_, bias1, inv, nullptr, 0, 1.0f, 1);
    // out = Wc2@h + bc2 + desc1
    gemm4<<<dim3(16, 2, B_), 256>>>(Wc2, 2 * C_, h, PB2, h, PB2, 2 * C_, 2 * C_, N_,
                                    out, PB, N_, bc2, nullptr, desc1, PB, 1.0f, 0);
}

// round 11
// speedup vs baseline: 1.0340x; 1.0340x over previous
#include <cuda_runtime.h>
#include <cstdint>

#define B_ 8
#define C_ 256
#define D_ 64
#define N_ 2048
#define M_ 2048

typedef unsigned long long ull;

__device__ float g_q[B_ * C_ * N_];
__device__ float g_k[B_ * C_ * M_];
__device__ float g_v[B_ * C_ * M_];
__device__ float g_attn[B_ * C_ * N_];
__device__ float g_h[B_ * 2 * C_ * N_];
__device__ float g_bias1[2 * C_];
__device__ float g_inv[2 * C_];
__device__ float g_Wcomb[2 * C_ * 2 * C_];   // [512][512]: [Wc1a | Wc1b@Wm]

// ---------------- packed f32x2 primitives ---------------------------------------
__device__ __forceinline__ ull ffma2(ull a, ull b, ull c) {
    ull d; asm("fma.rn.f32x2 %0,%1,%2,%3;" : "=l"(d) : "l"(a), "l"(b), "l"(c)); return d;
}
__device__ __forceinline__ ull fadd2(ull a, ull b) {
    ull d; asm("add.rn.f32x2 %0,%1,%2;" : "=l"(d) : "l"(a), "l"(b)); return d;
}
__device__ __forceinline__ ull fsub2(ull a, ull b) {
    ull d; asm("sub.rn.f32x2 %0,%1,%2;" : "=l"(d) : "l"(a), "l"(b)); return d;
}
__device__ __forceinline__ ull fmul2(ull a, ull b) {
    ull d; asm("mul.rn.f32x2 %0,%1,%2;" : "=l"(d) : "l"(a), "l"(b)); return d;
}
__device__ __forceinline__ ull pack2(float x) {
    ull d; asm("mov.b64 %0,{%1,%1};" : "=l"(d) : "f"(x)); return d;
}
__device__ __forceinline__ void unpack2(ull v, float& lo, float& hi) {
    asm("mov.b64 {%0,%1},%2;" : "=f"(lo), "=f"(hi) : "l"(v));
}
__device__ __forceinline__ void unpack2u(ull v, uint32_t& lo, uint32_t& hi) {
    asm("mov.b64 {%0,%1},%2;" : "=r"(lo), "=r"(hi) : "l"(v));
}
__device__ __forceinline__ ull pack2u(uint32_t lo, uint32_t hi) {
    ull d; asm("mov.b64 %0,{%1,%2};" : "=l"(d) : "r"(lo), "r"(hi)); return d;
}
__device__ __forceinline__ ull d2u(double x) { return __double_as_longlong(x); }

struct ExpC { ull c5, c4, c3, c2, c1, c0, mag, nmag; };
__device__ __forceinline__ ull exp2pk(ull t2, const ExpC& E) {
    ull r2 = fadd2(t2, E.mag);
    ull g2 = fadd2(r2, E.nmag);
    ull f2 = fsub2(t2, g2);
    ull p2 = ffma2(E.c5, f2, E.c4);
    p2 = ffma2(p2, f2, E.c3);
    p2 = ffma2(p2, f2, E.c2);
    p2 = ffma2(p2, f2, E.c1);
    p2 = ffma2(p2, f2, E.c0);
    uint32_t ilo, ihi;
    unpack2u(r2, ilo, ihi);
    uint32_t slo = (ilo + (127u - 0x400000u)) << 23;
    uint32_t shi = (ihi + (127u - 0x400000u)) << 23;
    return fmul2(p2, pack2u(slo, shi));
}

// ---------------- fold: BN + Wc1b@bm into bias1; copy Wc1a into g_Wcomb ----------
__global__ void fold_kernel(const float* __restrict__ Wc1, const float* __restrict__ bc1,
                            const float* __restrict__ bm,
                            const float* __restrict__ gamma, const float* __restrict__ beta,
                            const float* __restrict__ mean, const float* __restrict__ var) {
    int o = blockIdx.x * blockDim.x + threadIdx.x;
    if (o >= 2 * C_) return;
    float inv = gamma[o] * rsqrtf(var[o] + 1e-5f);
    g_inv[o] = inv;
    float s = 0.0f;
    const float* wrow = Wc1 + (size_t)o * (2 * C_) + C_;
#pragma unroll 4
    for (int j = 0; j < C_; j++) s = fmaf(wrow[j], bm[j], s);
    g_bias1[o] = inv * (bc1[o] + s - mean[o]) + beta[o];
}

__global__ void combcopy_kernel(const float* __restrict__ Wc1) {
    const int o = blockIdx.x;
    const int t = threadIdx.x;
    g_Wcomb[(size_t)o * (2 * C_) + t] = Wc1[(size_t)o * (2 * C_) + t];
}

// ---------------- wfold: g_Wcomb[:,256:512] = Wc1b @ Wm (64x64 tiles, 32 CTAs) ---
__global__ void __launch_bounds__(256) wfold_kernel(const float* __restrict__ Wc1,
                                                    const float* __restrict__ Wm) {
    __shared__ float sA[16][64];   // [k][o]
    __shared__ float sB[16][64];   // [k][j]
    const int tid = threadIdx.x;
    const int tx = tid & 15, ty = tid >> 4;
    const int j0 = blockIdx.x * 64, o0 = blockIdx.y * 64;

    float acc[4][4] = {};
    const int ar = tid >> 2;        // o 0..63
    const int ac = (tid & 3) << 2;  // k 0,4,8,12
    const int br = tid >> 4;        // k 0..15
    const int bc = (tid & 15) << 2; // j

    for (int kk = 0; kk < C_; kk += 16) {
        const float4 a4 = *(const float4*)(Wc1 + (size_t)(o0 + ar) * (2 * C_) + C_ + kk + ac);
        sA[ac + 0][ar] = a4.x; sA[ac + 1][ar] = a4.y;
        sA[ac + 2][ar] = a4.z; sA[ac + 3][ar] = a4.w;
        *(float4*)&sB[br][bc] = *(const float4*)(Wm + (size_t)(kk + br) * C_ + j0 + bc);
        __syncthreads();
#pragma unroll
        for (int k = 0; k < 16; k++) {
            const float4 av = *(const float4*)&sA[k][ty << 2];
            const float4 bv = *(const float4*)&sB[k][tx << 2];
            const float aa[4] = {av.x, av.y, av.z, av.w};
            const float bb[4] = {bv.x, bv.y, bv.z, bv.w};
#pragma unroll
            for (int a = 0; a < 4; a++)
#pragma unroll
                for (int j = 0; j < 4; j++) acc[a][j] = fmaf(aa[a], bb[j], acc[a][j]);
        }
        __syncthreads();
    }
#pragma unroll
    for (int a = 0; a < 4; a++) {
        const int o = o0 + (ty << 2) + a;
        float4 o4;
        o4.x = acc[a][0]; o4.y = acc[a][1]; o4.z = acc[a][2]; o4.w = acc[a][3];
        *(float4*)&g_Wcomb[(size_t)o * (2 * C_) + C_ + j0 + (tx << 2)] = o4;
    }
}

// ---------------- fused QKV GEMM ---------------------------------------------------
__global__ void __launch_bounds__(256, 2) qkv_gemm(
    const float* __restrict__ desc1, const float* __restrict__ desc2,
    const float* __restrict__ Wq, const float* __restrict__ bq,
    const float* __restrict__ Wk, const float* __restrict__ bk,
    const float* __restrict__ Wv, const float* __restrict__ bv,
    const float* __restrict__ weight_v,
    float* __restrict__ Yq, float* __restrict__ Yk, float* __restrict__ Yv,
    float qscale) {
    __shared__ ull   sW2[2][16][128];
    __shared__ float sX[2][16][128];
    const int tid = threadIdx.x;
    const int tx = tid & 15, ty = tid >> 4;
    const int n0 = blockIdx.x * 128;
    const int sel = blockIdx.y >> 1;
    const int o0 = (blockIdx.y & 1) * 128;
    const int bz = blockIdx.z;

    const float* W = (sel == 0) ? Wq : (sel == 1) ? Wk : Wv;
    const float* bias = (sel == 0) ? bq : (sel == 1) ? bk : bv;
    const float* X = (sel == 0) ? desc1 : desc2;
    float* Y = (sel == 0) ? Yq : (sel == 1) ? Yk : Yv;
    const float outscale = (sel == 0) ? qscale : 1.0f;
    const float* colscale = (sel == 2) ? (weight_v + (size_t)bz * M_) : nullptr;
    const float* Xb = X + (size_t)bz * ((long long)C_ * N_);

    const int wr = tid >> 1;
    const int wc = (tid & 1) * 8;
    const float* Wp = W + (size_t)(o0 + wr) * C_ + wc;
    const int xr0 = tid >> 5;
    const int xc0 = (tid & 31) * 4;

    float wbuf[8]; float4 xbuf[2];
    {
        const float4 a = *(const float4*)(Wp);
        const float4 b = *(const float4*)(Wp + 4);
        wbuf[0] = a.x; wbuf[1] = a.y; wbuf[2] = a.z; wbuf[3] = a.w;
        wbuf[4] = b.x; wbuf[5] = b.y; wbuf[6] = b.z; wbuf[7] = b.w;
#pragma unroll
        for (int l = 0; l < 2; l++)
            xbuf[l] = *(const float4*)(Xb + (size_t)(xr0 + l * 8) * N_ + n0 + xc0);
#pragma unroll
        for (int i = 0; i < 8; i++) sW2[0][wc + i][wr] = pack2(wbuf[i]);
#pragma unroll
        for (int l = 0; l < 2; l++) *(float4*)&sX[0][xr0 + l * 8][xc0] = xbuf[l];
    }
    __syncthreads();

    ull acc[8][4];
#pragma unroll
    for (int a = 0; a < 8; a++)
#pragma unroll
        for (int j = 0; j < 4; j++) acc[a][j] = 0ull;

    int buf = 0;
    for (int blk = 0; blk < 16; blk++) {
        const bool more = (blk + 1 < 16);
        if (more) {
            const int kk = (blk + 1) << 4;
            const float4 a = *(const float4*)(Wp + kk);
            const float4 b = *(const float4*)(Wp + kk + 4);
            wbuf[0] = a.x; wbuf[1] = a.y; wbuf[2] = a.z; wbuf[3] = a.w;
            wbuf[4] = b.x; wbuf[5] = b.y; wbuf[6] = b.z; wbuf[7] = b.w;
#pragma unroll
            for (int l = 0; l < 2; l++)
                xbuf[l] = *(const float4*)(Xb + (size_t)(kk + xr0 + l * 8) * N_ + n0 + xc0);
        }
#pragma unroll
        for (int k = 0; k < 16; k++) {
            const ulonglong2 wA = *(const ulonglong2*)&sW2[buf][k][ty * 8];
            const ulonglong2 wB = *(const ulonglong2*)&sW2[buf][k][ty * 8 + 2];
            const ulonglong2 wC = *(const ulonglong2*)&sW2[buf][k][ty * 8 + 4];
            const ulonglong2 wD = *(const ulonglong2*)&sW2[buf][k][ty * 8 + 6];
            const double2 xa = *(const double2*)&sX[buf][k][tx * 4];
            const double2 xb = *(const double2*)&sX[buf][k][64 + tx * 4];
            const ull x4[4] = {d2u(xa.x), d2u(xa.y), d2u(xb.x), d2u(xb.y)};
            const ull wv2[8] = {wA.x, wA.y, wB.x, wB.y, wC.x, wC.y, wD.x, wD.y};
#pragma unroll
            for (int a = 0; a < 8; a++)
#pragma unroll
                for (int j = 0; j < 4; j++) acc[a][j] = ffma2(wv2[a], x4[j], acc[a][j]);
        }
        if (more) {
#pragma unroll
            for (int i = 0; i < 8; i++) sW2[buf ^ 1][wc + i][wr] = pack2(wbuf[i]);
#pragma unroll
            for (int l = 0; l < 2; l++) *(float4*)&sX[buf ^ 1][xr0 + l * 8][xc0] = xbuf[l];
        }
        __syncthreads();
        buf ^= 1;
    }

    const int nA = n0 + tx * 4, nB = n0 + 64 + tx * 4;
    float cs[8];
#pragma unroll
    for (int j = 0; j < 8; j++) cs[j] = 1.0f;
    if (colscale) {
        const float4 ca = *(const float4*)(colscale + nA);
        const float4 cb = *(const float4*)(colscale + nB);
        cs[0] = ca.x; cs[1] = ca.y; cs[2] = ca.z; cs[3] = ca.w;
        cs[4] = cb.x; cs[5] = cb.y; cs[6] = cb.z; cs[7] = cb.w;
    }
#pragma unroll
    for (int a = 0; a < 8; a++) {
        const int o = o0 + ty * 8 + a;
        float t[8];
        unpack2(acc[a][0], t[0], t[1]);
        unpack2(acc[a][1], t[2], t[3]);
        unpack2(acc[a][2], t[4], t[5]);
        unpack2(acc[a][3], t[6], t[7]);
        const float bo = bias[o];
#pragma unroll
        for (int j = 0; j < 8; j++) t[j] = (t[j] + bo) * outscale * cs[j];
        float* yp = Y + (size_t)bz * ((long long)C_ * N_) + (size_t)o * N_;
        float4 oa4, ob4;
        oa4.x = t[0]; oa4.y = t[1]; oa4.z = t[2]; oa4.w = t[3];
        ob4.x = t[4]; ob4.y = t[5]; ob4.z = t[6]; ob4.w = t[7];
        *(float4*)(yp + nA) = oa4;
        *(float4*)(yp + nB) = ob4;
    }
}

// ---------------- GEMM v4 + ldY ---------------------------------------------------
__global__ void __launch_bounds__(256, 2) gemm4(
    const float* __restrict__ W, int ldW,
    const float* __restrict__ X0, long long xbs0,
    const float* __restrict__ X1, long long xbs1, int K0,
    int CIN, int L,
    float* __restrict__ Y, long long ybs, int ldY,
    const float* __restrict__ bias,
    const float* __restrict__ rowscale,
    const float* __restrict__ resid, long long rbs,
    float outscale, int relu) {
    __shared__ ull   sW2[2][16][128];
    __shared__ float sX[2][16][128];
    const int tid = threadIdx.x;
    const int tx = tid & 15, ty = tid >> 4;
    const int n0 = blockIdx.x * 128, o0 = blockIdx.y * 128;
    const int bz = blockIdx.z;

    const int wr = tid >> 1;
    const int wc = (tid & 1) * 8;
    const float* Wp = W + (size_t)(o0 + wr) * ldW + wc;
    const int xr0 = tid >> 5;
    const int xc0 = (tid & 31) * 4;

    float wbuf[8]; float4 xbuf[2];
    {
        const float4 a = *(const float4*)(Wp);
        const float4 b = *(const float4*)(Wp + 4);
        wbuf[0] = a.x; wbuf[1] = a.y; wbuf[2] = a.z; wbuf[3] = a.w;
        wbuf[4] = b.x; wbuf[5] = b.y; wbuf[6] = b.z; wbuf[7] = b.w;
#pragma unroll
        for (int l = 0; l < 2; l++) {
            const int k = xr0 + l * 8;
            const float* xs = (k < K0)
                ? X0 + (size_t)bz * xbs0 + (size_t)k * L
                : X1 + (size_t)bz * xbs1 + (size_t)(k - K0) * L;
            xbuf[l] = *(const float4*)(xs + n0 + xc0);
        }
#pragma unroll
        for (int i = 0; i < 8; i++) sW2[0][wc + i][wr] = pack2(wbuf[i]);
#pragma unroll
        for (int l = 0; l < 2; l++) *(float4*)&sX[0][xr0 + l * 8][xc0] = xbuf[l];
    }
    __syncthreads();

    ull acc[8][4];
#pragma unroll
    for (int a = 0; a < 8; a++)
#pragma unroll
        for (int j = 0; j < 4; j++) acc[a][j] = 0ull;

    const int nblk = CIN >> 4;
    int buf = 0;
    for (int blk = 0; blk < nblk; blk++) {
        const bool more = (blk + 1 < nblk);
        if (more) {
            const int kk = (blk + 1) << 4;
            const float4 a = *(const float4*)(Wp + kk);
            const float4 b = *(const float4*)(Wp + kk + 4);
            wbuf[0] = a.x; wbuf[1] = a.y; wbuf[2] = a.z; wbuf[3] = a.w;
            wbuf[4] = b.x; wbuf[5] = b.y; wbuf[6] = b.z; wbuf[7] = b.w;
#pragma unroll
            for (int l = 0; l < 2; l++) {
                const int k = kk + xr0 + l * 8;
                const float* xs = (k < K0)
                    ? X0 + (size_t)bz * xbs0 + (size_t)k * L
                    : X1 + (size_t)bz * xbs1 + (size_t)(k - K0) * L;
                xbuf[l] = *(const float4*)(xs + n0 + xc0);
            }
        }
#pragma unroll
        for (int k = 0; k < 16; k++) {
            const ulonglong2 wA = *(const ulonglong2*)&sW2[buf][k][ty * 8];
            const ulonglong2 wB = *(const ulonglong2*)&sW2[buf][k][ty * 8 + 2];
            const ulonglong2 wC = *(const ulonglong2*)&sW2[buf][k][ty * 8 + 4];
            const ulonglong2 wD = *(const ulonglong2*)&sW2[buf][k][ty * 8 + 6];
            const double2 xa = *(const double2*)&sX[buf][k][tx * 4];
            const double2 xb = *(const double2*)&sX[buf][k][64 + tx * 4];
            const ull x4[4] = {d2u(xa.x), d2u(xa.y), d2u(xb.x), d2u(xb.y)};
            const ull wv2[8] = {wA.x, wA.y, wB.x, wB.y, wC.x, wC.y, wD.x, wD.y};
#pragma unroll
            for (int a = 0; a < 8; a++)
#pragma unroll
                for (int j = 0; j < 4; j++) acc[a][j] = ffma2(wv2[a], x4[j], acc[a][j]);
        }
        if (more) {
#pragma unroll
            for (int i = 0; i < 8; i++) sW2[buf ^ 1][wc + i][wr] = pack2(wbuf[i]);
#pragma unroll
            for (int l = 0; l < 2; l++) *(float4*)&sX[buf ^ 1][xr0 + l * 8][xc0] = xbuf[l];
        }
        __syncthreads();
        buf ^= 1;
    }

    const int nA = n0 + tx * 4, nB = n0 + 64 + tx * 4;
#pragma unroll
    for (int a = 0; a < 8; a++) {
        const int o = o0 + ty * 8 + a;
        float t[8];
        unpack2(acc[a][0], t[0], t[1]);
        unpack2(acc[a][1], t[2], t[3]);
        unpack2(acc[a][2], t[4], t[5]);
        unpack2(acc[a][3], t[6], t[7]);
        const float rs = rowscale ? rowscale[o] : 1.0f;
        const float bo = bias ? bias[o] : 0.0f;
#pragma unroll
        for (int j = 0; j < 8; j++) t[j] = fmaf(t[j], rs, bo) * outscale;
        if (relu) {
#pragma unroll
            for (int j = 0; j < 8; j++) t[j] = fmaxf(t[j], 0.0f);
        }
        if (resid) {
            const float4 ra = *(const float4*)(resid + (size_t)bz * rbs + (size_t)o * ldY + nA);
            const float4 rb = *(const float4*)(resid + (size_t)bz * rbs + (size_t)o * ldY + nB);
            t[0] += ra.x; t[1] += ra.y; t[2] += ra.z; t[3] += ra.w;
            t[4] += rb.x; t[5] += rb.y; t[6] += rb.z; t[7] += rb.w;
        }
        float4 oa4, ob4;
        oa4.x = t[0]; oa4.y = t[1]; oa4.z = t[2]; oa4.w = t[3];
        ob4.x = t[4]; ob4.y = t[5]; ob4.z = t[6]; ob4.w = t[7];
        *(float4*)(Y + (size_t)bz * ybs + (size_t)o * ldY + nA) = oa4;
        *(float4*)(Y + (size_t)bz * ybs + (size_t)o * ldY + nB) = ob4;
    }
}

// ---------------- flash128 (R9 exact): 128-n tile, f32x2, no-max softmax ---------
#define F_SQ 0
#define F_SK (64 * 128)
#define F_SV (F_SK + 64 * 68)
#define F_SPT (F_SV + 64 * 68)
#define F_SL (F_SPT + 64 * 130)
#define F_SMEM_FLOATS (F_SL + 128)
#define F_SMEM_BYTES (F_SMEM_FLOATS * 4)

__global__ void __launch_bounds__(256, 2) flash128_kernel() {
    extern __shared__ float sm[];
    float* sQ = sm + F_SQ;
    float* sK = sm + F_SK;
    float* sV = sm + F_SV;
    float* sPT = sm + F_SPT;
    float* sL = sm + F_SL;

    const int tid = threadIdx.x;
    const int tx = tid & 15, ty = tid >> 4;
    const int b = blockIdx.y >> 2, h = blockIdx.y & 3;
    const size_t base = ((size_t)b * C_ + h * D_) * (size_t)N_;
    const float* qg = g_q + base + blockIdx.x * 128;
    const float* kg = g_k + base;
    const float* vg = g_v + base;
    float* og = g_attn + base + blockIdx.x * 128;

    ExpC E;
    E.c5 = pack2(1.3333558e-3f); E.c4 = pack2(9.6181291e-3f);
    E.c3 = pack2(5.5504109e-2f); E.c2 = pack2(2.4022651e-1f);
    E.c1 = pack2(6.9314718e-1f); E.c0 = pack2(1.0f);
    E.mag = pack2(12582912.0f);  E.nmag = pack2(-12582912.0f);

#pragma unroll
    for (int l = 0; l < 8; l++) {
        const int idx = tid + l * 256;
        const int r = idx >> 5, c4 = idx & 31;
        *(float4*)&sQ[r * 128 + c4 * 4] = *(const float4*)(qg + (size_t)r * N_ + c4 * 4);
    }

    ull oa2[4][4];
    ull lsum2[8];
#pragma unroll
    for (int a = 0; a < 4; a++)
#pragma unroll
        for (int j = 0; j < 4; j++) oa2[a][j] = 0ull;
#pragma unroll
    for (int i = 0; i < 8; i++) lsum2[i] = 0ull;
    __syncthreads();

    const int stag = tx >> 2;

    for (int mt = 0; mt < M_; mt += 64) {
#pragma unroll
        for (int l = 0; l < 4; l++) {
            const int idx = tid + l * 256;
            const int r = idx >> 4, c = (idx & 15) << 2;
            *(float4*)&sK[r * 68 + c] = *(const float4*)(kg + (size_t)r * M_ + mt + c);
            *(float4*)&sV[r * 68 + c] = *(const float4*)(vg + (size_t)r * M_ + mt + c);
        }
        __syncthreads();

        ull s2[16];
#pragma unroll
        for (int i = 0; i < 16; i++) s2[i] = 0ull;
#pragma unroll 4
        for (int d = 0; d < 64; d++) {
            const double2 kd = *(const double2*)&sK[d * 68 + (tx << 2)];
            const ull k0 = d2u(kd.x), k1 = d2u(kd.y);
            const float4 qa = *(const float4*)&sQ[d * 128 + (ty << 2)];
            const float4 qb = *(const float4*)&sQ[d * 128 + 64 + (ty << 2)];
            const float qf[8] = {qa.x, qa.y, qa.z, qa.w, qb.x, qb.y, qb.z, qb.w};
#pragma unroll
            for (int i = 0; i < 8; i++) {
                const ull qp = pack2(qf[i]);
                s2[i * 2 + 0] = ffma2(qp, k0, s2[i * 2 + 0]);
                s2[i * 2 + 1] = ffma2(qp, k1, s2[i * 2 + 1]);
            }
        }

#pragma unroll
        for (int i = 0; i < 8; i++) {
            const ull p0 = exp2pk(s2[i * 2 + 0], E);
            const ull p1 = exp2pk(s2[i * 2 + 1], E);
            lsum2[i] = fadd2(lsum2[i], fadd2(p0, p1));
            float pf[4];
            unpack2(p0, pf[0], pf[1]);
            unpack2(p1, pf[2], pf[3]);
            const int n = (i >> 2) * 64 + (ty << 2) + (i & 3);
#pragma unroll
            for (int jl = 0; jl < 4; jl++) {
                const int jj = (jl + stag) & 3;
                sPT[(4 * tx + jj) * 130 + n] = pf[jj];
            }
        }
        __syncthreads();

#pragma unroll 2
        for (int mb = 0; mb < 64; mb += 4) {
            float4 vv4[4];
#pragma unroll
            for (int a = 0; a < 4; a++)
                vv4[a] = *(const float4*)&sV[((ty << 2) + a) * 68 + mb];
            const float* vvf = (const float*)vv4;
#pragma unroll
            for (int mm = 0; mm < 4; mm++) {
                const float* ptrow = &sPT[(mb + mm) * 130];
                const ull p0 = *(const ull*)&ptrow[(tx << 2)];
                const ull p1 = *(const ull*)&ptrow[(tx << 2) + 2];
                const ull p2 = *(const ull*)&ptrow[64 + (tx << 2)];
                const ull p3 = *(const ull*)&ptrow[64 + (tx << 2) + 2];
#pragma unroll
                for (int a = 0; a < 4; a++) {
                    const ull vb = pack2(vvf[a * 4 + mm]);
                    oa2[a][0] = ffma2(vb, p0, oa2[a][0]);
                    oa2[a][1] = ffma2(vb, p1, oa2[a][1]);
                    oa2[a][2] = ffma2(vb, p2, oa2[a][2]);
                    oa2[a][3] = ffma2(vb, p3, oa2[a][3]);
                }
            }
        }
        __syncthreads();
    }

#pragma unroll
    for (int i = 0; i < 8; i++) {
        float lo, hi;
        unpack2(lsum2[i], lo, hi);
        float l = lo + hi;
        l += __shfl_xor_sync(0xffffffffu, l, 1);
        l += __shfl_xor_sync(0xffffffffu, l, 2);
        l += __shfl_xor_sync(0xffffffffu, l, 4);
        l += __shfl_xor_sync(0xffffffffu, l, 8);
        if (tx == 0) sL[(i >> 2) * 64 + (ty << 2) + (i & 3)] = l;
    }
    __syncthreads();
    float li[8];
#pragma unroll
    for (int j = 0; j < 4; j++) {
        li[j] = 1.0f / sL[(tx << 2) + j];
        li[4 + j] = 1.0f / sL[64 + (tx << 2) + j];
    }
#pragma unroll
    for (int a = 0; a < 4; a++) {
        const int dd = (ty << 2) + a;
        float t[8];
        unpack2(oa2[a][0], t[0], t[1]);
        unpack2(oa2[a][1], t[2], t[3]);
        unpack2(oa2[a][2], t[4], t[5]);
        unpack2(oa2[a][3], t[6], t[7]);
        float4 o4a, o4b;
        o4a.x = t[0] * li[0]; o4a.y = t[1] * li[1];
        o4a.z = t[2] * li[2]; o4a.w = t[3] * li[3];
        o4b.x = t[4] * li[4]; o4b.y = t[5] * li[5];
        o4b.z = t[6] * li[6]; o4b.w = t[7] * li[7];
        *(float4*)(og + (size_t)dd * N_ + (tx << 2)) = o4a;
        *(float4*)(og + (size_t)dd * N_ + 64 + (tx << 2)) = o4b;
    }
}

// ---------------- launcher -------------------------------------------------------
extern "C" void kernel_launch(void* const* d_in, const int* in_sizes, int n_in,
                              void* d_out, int out_size) {
    const float* desc1 = (const float*)d_in[0];
    const float* desc2 = (const float*)d_in[1];
    const float* weight_v = (const float*)d_in[2];
    const float* Wq = (const float*)d_in[3];
    const float* bq = (const float*)d_in[4];
    const float* Wk = (const float*)d_in[5];
    const float* bk = (const float*)d_in[6];
    const float* Wv = (const float*)d_in[7];
    const float* bv = (const float*)d_in[8];
    const float* Wm = (const float*)d_in[9];
    const float* bm = (const float*)d_in[10];
    const float* Wc1 = (const float*)d_in[11];
    const float* bc1 = (const float*)d_in[12];
    const float* gamma = (const float*)d_in[13];
    const float* beta  = (const float*)d_in[14];
    const float* mean  = (const float*)d_in[15];
    const float* var   = (const float*)d_in[16];
    const float* Wc2 = (const float*)d_in[17];
    const float* bc2 = (const float*)d_in[18];
    float* out = (float*)d_out;

    float *q, *k, *v, *attn, *h, *bias1, *inv, *wcomb;
    cudaGetSymbolAddress((void**)&q, g_q);
    cudaGetSymbolAddress((void**)&k, g_k);
    cudaGetSymbolAddress((void**)&v, g_v);
    cudaGetSymbolAddress((void**)&attn, g_attn);
    cudaGetSymbolAddress((void**)&h, g_h);
    cudaGetSymbolAddress((void**)&bias1, g_bias1);
    cudaGetSymbolAddress((void**)&inv, g_inv);
    cudaGetSymbolAddress((void**)&wcomb, g_Wcomb);

    cudaFuncSetAttribute(flash128_kernel, cudaFuncAttributeMaxDynamicSharedMemorySize, F_SMEM_BYTES);

    const long long PB = (long long)C_ * N_;
    const long long PB2 = (long long)2 * C_ * N_;

    const float QSCALE = 0.125f * 1.4426950408889634f;

    // weight preprocessing: bias1 (BN + Wc1b@bm), Wcomb = [Wc1a | Wc1b@Wm]
    fold_kernel<<<2, 256>>>(Wc1, bc1, bm, gamma, beta, mean, var);
    combcopy_kernel<<<512, 256>>>(Wc1);
    wfold_kernel<<<dim3(4, 8), 256>>>(Wc1, Wm);

    // fused q,k,v projections
    qkv_gemm<<<dim3(N_ / 128, 6, B_), 256>>>(desc1, desc2, Wq, bq, Wk, bk, Wv, bv,
                                             weight_v, q, k, v, QSCALE);
    // attention
    flash128_kernel<<<dim3(N_ / 128, B_ * 4), 256, F_SMEM_BYTES>>>();
    // h = relu( inv * (Wcomb @ [desc1; attn]) + bias1 )   (Wm GEMM folded away)
    gemm4<<<dim3(16, 4, B_), 256>>>(wcomb, 2 * C_, desc1, PB, attn, PB, C_, 2 * C_, N_,
                                    h, PB2, N_, bias1, inv, nullptr, 0, 1.0f, 1);
    // out = Wc2@h + bc2 + desc1
    gemm4<<<dim3(16, 2, B_), 256>>>(Wc2, 2 * C_, h, PB2, h, PB2, 2 * C_, 2 * C_, N_,
                                    out, PB, N_, bc2, nullptr, desc1, PB, 1.0f, 0);
}

// round 12
// speedup vs baseline: 1.0781x; 1.0426x over previous
#include <cuda_runtime.h>
#include <cstdint>

#define B_ 8
#define C_ 256
#define D_ 64
#define N_ 2048
#define M_ 2048

typedef unsigned long long ull;

__device__ float g_q[B_ * C_ * N_];
__device__ float g_k[B_ * C_ * M_];
__device__ float g_v[B_ * C_ * M_];
__device__ float g_attn[B_ * C_ * N_];
__device__ float g_h[B_ * 2 * C_ * N_];
__device__ float g_bias1[2 * C_];
__device__ float g_inv[2 * C_];
__device__ float g_Wcomb[2 * C_ * 2 * C_];   // [512][512]: [Wc1a | Wc1b@Wm]

// ---------------- packed f32x2 primitives ---------------------------------------
__device__ __forceinline__ ull ffma2(ull a, ull b, ull c) {
    ull d; asm("fma.rn.f32x2 %0,%1,%2,%3;" : "=l"(d) : "l"(a), "l"(b), "l"(c)); return d;
}
__device__ __forceinline__ ull fadd2(ull a, ull b) {
    ull d; asm("add.rn.f32x2 %0,%1,%2;" : "=l"(d) : "l"(a), "l"(b)); return d;
}
__device__ __forceinline__ ull fsub2(ull a, ull b) {
    ull d; asm("sub.rn.f32x2 %0,%1,%2;" : "=l"(d) : "l"(a), "l"(b)); return d;
}
__device__ __forceinline__ ull fmul2(ull a, ull b) {
    ull d; asm("mul.rn.f32x2 %0,%1,%2;" : "=l"(d) : "l"(a), "l"(b)); return d;
}
__device__ __forceinline__ ull pack2(float x) {
    ull d; asm("mov.b64 %0,{%1,%1};" : "=l"(d) : "f"(x)); return d;
}
__device__ __forceinline__ void unpack2(ull v, float& lo, float& hi) {
    asm("mov.b64 {%0,%1},%2;" : "=f"(lo), "=f"(hi) : "l"(v));
}
__device__ __forceinline__ void unpack2u(ull v, uint32_t& lo, uint32_t& hi) {
    asm("mov.b64 {%0,%1},%2;" : "=r"(lo), "=r"(hi) : "l"(v));
}
__device__ __forceinline__ ull pack2u(uint32_t lo, uint32_t hi) {
    ull d; asm("mov.b64 %0,{%1,%2};" : "=l"(d) : "r"(lo), "r"(hi)); return d;
}
__device__ __forceinline__ ull d2u(double x) { return __double_as_longlong(x); }

struct ExpC { ull c5, c4, c3, c2, c1, c0, mag, nmag; };
__device__ __forceinline__ ull exp2pk(ull t2, const ExpC& E) {
    ull r2 = fadd2(t2, E.mag);
    ull g2 = fadd2(r2, E.nmag);
    ull f2 = fsub2(t2, g2);
    ull p2 = ffma2(E.c5, f2, E.c4);
    p2 = ffma2(p2, f2, E.c3);
    p2 = ffma2(p2, f2, E.c2);
    p2 = ffma2(p2, f2, E.c1);
    p2 = ffma2(p2, f2, E.c0);
    uint32_t ilo, ihi;
    unpack2u(r2, ilo, ihi);
    uint32_t slo = (ilo + (127u - 0x400000u)) << 23;
    uint32_t shi = (ihi + (127u - 0x400000u)) << 23;
    return fmul2(p2, pack2u(slo, shi));
}

// ---------------- fold: BN + Wc1b@bm into bias1; copy Wc1a into g_Wcomb ----------
__global__ void fold_kernel(const float* __restrict__ Wc1, const float* __restrict__ bc1,
                            const float* __restrict__ bm,
                            const float* __restrict__ gamma, const float* __restrict__ beta,
                            const float* __restrict__ mean, const float* __restrict__ var) {
    int o = blockIdx.x * blockDim.x + threadIdx.x;
    if (o >= 2 * C_) return;
    float inv = gamma[o] * rsqrtf(var[o] + 1e-5f);
    g_inv[o] = inv;
    float s = 0.0f;
    const float* wrow = Wc1 + (size_t)o * (2 * C_) + C_;
#pragma unroll 4
    for (int j = 0; j < C_; j++) s = fmaf(wrow[j], bm[j], s);
    g_bias1[o] = inv * (bc1[o] + s - mean[o]) + beta[o];
}

__global__ void combcopy_kernel(const float* __restrict__ Wc1) {
    const int o = blockIdx.x;
    const int t = threadIdx.x;
    g_Wcomb[(size_t)o * (2 * C_) + t] = Wc1[(size_t)o * (2 * C_) + t];
}

// ---------------- wfold: g_Wcomb[:,256:512] = Wc1b @ Wm (64x64 tiles, 32 CTAs) ---
__global__ void __launch_bounds__(256) wfold_kernel(const float* __restrict__ Wc1,
                                                    const float* __restrict__ Wm) {
    __shared__ float sA[16][64];
    __shared__ float sB[16][64];
    const int tid = threadIdx.x;
    const int tx = tid & 15, ty = tid >> 4;
    const int j0 = blockIdx.x * 64, o0 = blockIdx.y * 64;

    float acc[4][4] = {};
    const int ar = tid >> 2;
    const int ac = (tid & 3) << 2;
    const int br = tid >> 4;
    const int bc = (tid & 15) << 2;

    for (int kk = 0; kk < C_; kk += 16) {
        const float4 a4 = *(const float4*)(Wc1 + (size_t)(o0 + ar) * (2 * C_) + C_ + kk + ac);
        sA[ac + 0][ar] = a4.x; sA[ac + 1][ar] = a4.y;
        sA[ac + 2][ar] = a4.z; sA[ac + 3][ar] = a4.w;
        *(float4*)&sB[br][bc] = *(const float4*)(Wm + (size_t)(kk + br) * C_ + j0 + bc);
        __syncthreads();
#pragma unroll
        for (int k = 0; k < 16; k++) {
            const float4 av = *(const float4*)&sA[k][ty << 2];
            const float4 bv = *(const float4*)&sB[k][tx << 2];
            const float aa[4] = {av.x, av.y, av.z, av.w};
            const float bb[4] = {bv.x, bv.y, bv.z, bv.w};
#pragma unroll
            for (int a = 0; a < 4; a++)
#pragma unroll
                for (int j = 0; j < 4; j++) acc[a][j] = fmaf(aa[a], bb[j], acc[a][j]);
        }
        __syncthreads();
    }
#pragma unroll
    for (int a = 0; a < 4; a++) {
        const int o = o0 + (ty << 2) + a;
        float4 o4;
        o4.x = acc[a][0]; o4.y = acc[a][1]; o4.z = acc[a][2]; o4.w = acc[a][3];
        *(float4*)&g_Wcomb[(size_t)o * (2 * C_) + C_ + j0 + (tx << 2)] = o4;
    }
}

// ---------------- fused QKV GEMM ---------------------------------------------------
__global__ void __launch_bounds__(256, 2) qkv_gemm(
    const float* __restrict__ desc1, const float* __restrict__ desc2,
    const float* __restrict__ Wq, const float* __restrict__ bq,
    const float* __restrict__ Wk, const float* __restrict__ bk,
    const float* __restrict__ Wv, const float* __restrict__ bv,
    const float* __restrict__ weight_v,
    float* __restrict__ Yq, float* __restrict__ Yk, float* __restrict__ Yv,
    float qscale) {
    __shared__ ull   sW2[2][16][128];
    __shared__ float sX[2][16][128];
    const int tid = threadIdx.x;
    const int tx = tid & 15, ty = tid >> 4;
    const int n0 = blockIdx.x * 128;
    const int sel = blockIdx.y >> 1;
    const int o0 = (blockIdx.y & 1) * 128;
    const int bz = blockIdx.z;

    const float* W = (sel == 0) ? Wq : (sel == 1) ? Wk : Wv;
    const float* bias = (sel == 0) ? bq : (sel == 1) ? bk : bv;
    const float* X = (sel == 0) ? desc1 : desc2;
    float* Y = (sel == 0) ? Yq : (sel == 1) ? Yk : Yv;
    const float outscale = (sel == 0) ? qscale : 1.0f;
    const float* colscale = (sel == 2) ? (weight_v + (size_t)bz * M_) : nullptr;
    const float* Xb = X + (size_t)bz * ((long long)C_ * N_);

    const int wr = tid >> 1;
    const int wc = (tid & 1) * 8;
    const float* Wp = W + (size_t)(o0 + wr) * C_ + wc;
    const int xr0 = tid >> 5;
    const int xc0 = (tid & 31) * 4;

    float wbuf[8]; float4 xbuf[2];
    {
        const float4 a = *(const float4*)(Wp);
        const float4 b = *(const float4*)(Wp + 4);
        wbuf[0] = a.x; wbuf[1] = a.y; wbuf[2] = a.z; wbuf[3] = a.w;
        wbuf[4] = b.x; wbuf[5] = b.y; wbuf[6] = b.z; wbuf[7] = b.w;
#pragma unroll
        for (int l = 0; l < 2; l++)
            xbuf[l] = *(const float4*)(Xb + (size_t)(xr0 + l * 8) * N_ + n0 + xc0);
#pragma unroll
        for (int i = 0; i < 8; i++) sW2[0][wc + i][wr] = pack2(wbuf[i]);
#pragma unroll
        for (int l = 0; l < 2; l++) *(float4*)&sX[0][xr0 + l * 8][xc0] = xbuf[l];
    }
    __syncthreads();

    ull acc[8][4];
#pragma unroll
    for (int a = 0; a < 8; a++)
#pragma unroll
        for (int j = 0; j < 4; j++) acc[a][j] = 0ull;

    int buf = 0;
    for (int blk = 0; blk < 16; blk++) {
        const bool more = (blk + 1 < 16);
        if (more) {
            const int kk = (blk + 1) << 4;
            const float4 a = *(const float4*)(Wp + kk);
            const float4 b = *(const float4*)(Wp + kk + 4);
            wbuf[0] = a.x; wbuf[1] = a.y; wbuf[2] = a.z; wbuf[3] = a.w;
            wbuf[4] = b.x; wbuf[5] = b.y; wbuf[6] = b.z; wbuf[7] = b.w;
#pragma unroll
            for (int l = 0; l < 2; l++)
                xbuf[l] = *(const float4*)(Xb + (size_t)(kk + xr0 + l * 8) * N_ + n0 + xc0);
        }
#pragma unroll
        for (int k = 0; k < 16; k++) {
            const ulonglong2 wA = *(const ulonglong2*)&sW2[buf][k][ty * 8];
            const ulonglong2 wB = *(const ulonglong2*)&sW2[buf][k][ty * 8 + 2];
            const ulonglong2 wC = *(const ulonglong2*)&sW2[buf][k][ty * 8 + 4];
            const ulonglong2 wD = *(const ulonglong2*)&sW2[buf][k][ty * 8 + 6];
            const double2 xa = *(const double2*)&sX[buf][k][tx * 4];
            const double2 xb = *(const double2*)&sX[buf][k][64 + tx * 4];
            const ull x4[4] = {d2u(xa.x), d2u(xa.y), d2u(xb.x), d2u(xb.y)};
            const ull wv2[8] = {wA.x, wA.y, wB.x, wB.y, wC.x, wC.y, wD.x, wD.y};
#pragma unroll
            for (int a = 0; a < 8; a++)
#pragma unroll
                for (int j = 0; j < 4; j++) acc[a][j] = ffma2(wv2[a], x4[j], acc[a][j]);
        }
        if (more) {
#pragma unroll
            for (int i = 0; i < 8; i++) sW2[buf ^ 1][wc + i][wr] = pack2(wbuf[i]);
#pragma unroll
            for (int l = 0; l < 2; l++) *(float4*)&sX[buf ^ 1][xr0 + l * 8][xc0] = xbuf[l];
        }
        __syncthreads();
        buf ^= 1;
    }

    const int nA = n0 + tx * 4, nB = n0 + 64 + tx * 4;
    float cs[8];
#pragma unroll
    for (int j = 0; j < 8; j++) cs[j] = 1.0f;
    if (colscale) {
        const float4 ca = *(const float4*)(colscale + nA);
        const float4 cb = *(const float4*)(colscale + nB);
        cs[0] = ca.x; cs[1] = ca.y; cs[2] = ca.z; cs[3] = ca.w;
        cs[4] = cb.x; cs[5] = cb.y; cs[6] = cb.z; cs[7] = cb.w;
    }
#pragma unroll
    for (int a = 0; a < 8; a++) {
        const int o = o0 + ty * 8 + a;
        float t[8];
        unpack2(acc[a][0], t[0], t[1]);
        unpack2(acc[a][1], t[2], t[3]);
        unpack2(acc[a][2], t[4], t[5]);
        unpack2(acc[a][3], t[6], t[7]);
        const float bo = bias[o];
#pragma unroll
        for (int j = 0; j < 8; j++) t[j] = (t[j] + bo) * outscale * cs[j];
        float* yp = Y + (size_t)bz * ((long long)C_ * N_) + (size_t)o * N_;
        float4 oa4, ob4;
        oa4.x = t[0]; oa4.y = t[1]; oa4.z = t[2]; oa4.w = t[3];
        ob4.x = t[4]; ob4.y = t[5]; ob4.z = t[6]; ob4.w = t[7];
        *(float4*)(yp + nA) = oa4;
        *(float4*)(yp + nB) = ob4;
    }
}

// ---------------- GEMM v4 + ldY ---------------------------------------------------
__global__ void __launch_bounds__(256, 2) gemm4(
    const float* __restrict__ W, int ldW,
    const float* __restrict__ X0, long long xbs0,
    const float* __restrict__ X1, long long xbs1, int K0,
    int CIN, int L,
    float* __restrict__ Y, long long ybs, int ldY,
    const float* __restrict__ bias,
    const float* __restrict__ rowscale,
    const float* __restrict__ resid, long long rbs,
    float outscale, int relu) {
    __shared__ ull   sW2[2][16][128];
    __shared__ float sX[2][16][128];
    const int tid = threadIdx.x;
    const int tx = tid & 15, ty = tid >> 4;
    const int n0 = blockIdx.x * 128, o0 = blockIdx.y * 128;
    const int bz = blockIdx.z;

    const int wr = tid >> 1;
    const int wc = (tid & 1) * 8;
    const float* Wp = W + (size_t)(o0 + wr) * ldW + wc;
    const int xr0 = tid >> 5;
    const int xc0 = (tid & 31) * 4;

    float wbuf[8]; float4 xbuf[2];
    {
        const float4 a = *(const float4*)(Wp);
        const float4 b = *(const float4*)(Wp + 4);
        wbuf[0] = a.x; wbuf[1] = a.y; wbuf[2] = a.z; wbuf[3] = a.w;
        wbuf[4] = b.x; wbuf[5] = b.y; wbuf[6] = b.z; wbuf[7] = b.w;
#pragma unroll
        for (int l = 0; l < 2; l++) {
            const int k = xr0 + l * 8;
            const float* xs = (k < K0)
                ? X0 + (size_t)bz * xbs0 + (size_t)k * L
                : X1 + (size_t)bz * xbs1 + (size_t)(k - K0) * L;
            xbuf[l] = *(const float4*)(xs + n0 + xc0);
        }
#pragma unroll
        for (int i = 0; i < 8; i++) sW2[0][wc + i][wr] = pack2(wbuf[i]);
#pragma unroll
        for (int l = 0; l < 2; l++) *(float4*)&sX[0][xr0 + l * 8][xc0] = xbuf[l];
    }
    __syncthreads();

    ull acc[8][4];
#pragma unroll
    for (int a = 0; a < 8; a++)
#pragma unroll
        for (int j = 0; j < 4; j++) acc[a][j] = 0ull;

    const int nblk = CIN >> 4;
    int buf = 0;
    for (int blk = 0; blk < nblk; blk++) {
        const bool more = (blk + 1 < nblk);
        if (more) {
            const int kk = (blk + 1) << 4;
            const float4 a = *(const float4*)(Wp + kk);
            const float4 b = *(const float4*)(Wp + kk + 4);
            wbuf[0] = a.x; wbuf[1] = a.y; wbuf[2] = a.z; wbuf[3] = a.w;
            wbuf[4] = b.x; wbuf[5] = b.y; wbuf[6] = b.z; wbuf[7] = b.w;
#pragma unroll
            for (int l = 0; l < 2; l++) {
                const int k = kk + xr0 + l * 8;
                const float* xs = (k < K0)
                    ? X0 + (size_t)bz * xbs0 + (size_t)k * L
                    : X1 + (size_t)bz * xbs1 + (size_t)(k - K0) * L;
                xbuf[l] = *(const float4*)(xs + n0 + xc0);
            }
        }
#pragma unroll
        for (int k = 0; k < 16; k++) {
            const ulonglong2 wA = *(const ulonglong2*)&sW2[buf][k][ty * 8];
            const ulonglong2 wB = *(const ulonglong2*)&sW2[buf][k][ty * 8 + 2];
            const ulonglong2 wC = *(const ulonglong2*)&sW2[buf][k][ty * 8 + 4];
            const ulonglong2 wD = *(const ulonglong2*)&sW2[buf][k][ty * 8 + 6];
            const double2 xa = *(const double2*)&sX[buf][k][tx * 4];
            const double2 xb = *(const double2*)&sX[buf][k][64 + tx * 4];
            const ull x4[4] = {d2u(xa.x), d2u(xa.y), d2u(xb.x), d2u(xb.y)};
            const ull wv2[8] = {wA.x, wA.y, wB.x, wB.y, wC.x, wC.y, wD.x, wD.y};
#pragma unroll
            for (int a = 0; a < 8; a++)
#pragma unroll
                for (int j = 0; j < 4; j++) acc[a][j] = ffma2(wv2[a], x4[j], acc[a][j]);
        }
        if (more) {
#pragma unroll
            for (int i = 0; i < 8; i++) sW2[buf ^ 1][wc + i][wr] = pack2(wbuf[i]);
#pragma unroll
            for (int l = 0; l < 2; l++) *(float4*)&sX[buf ^ 1][xr0 + l * 8][xc0] = xbuf[l];
        }
        __syncthreads();
        buf ^= 1;
    }

    const int nA = n0 + tx * 4, nB = n0 + 64 + tx * 4;
#pragma unroll
    for (int a = 0; a < 8; a++) {
        const int o = o0 + ty * 8 + a;
        float t[8];
        unpack2(acc[a][0], t[0], t[1]);
        unpack2(acc[a][1], t[2], t[3]);
        unpack2(acc[a][2], t[4], t[5]);
        unpack2(acc[a][3], t[6], t[7]);
        const float rs = rowscale ? rowscale[o] : 1.0f;
        const float bo = bias ? bias[o] : 0.0f;
#pragma unroll
        for (int j = 0; j < 8; j++) t[j] = fmaf(t[j], rs, bo) * outscale;
        if (relu) {
#pragma unroll
            for (int j = 0; j < 8; j++) t[j] = fmaxf(t[j], 0.0f);
        }
        if (resid) {
            const float4 ra = *(const float4*)(resid + (size_t)bz * rbs + (size_t)o * ldY + nA);
            const float4 rb = *(const float4*)(resid + (size_t)bz * rbs + (size_t)o * ldY + nB);
            t[0] += ra.x; t[1] += ra.y; t[2] += ra.z; t[3] += ra.w;
            t[4] += rb.x; t[5] += rb.y; t[6] += rb.z; t[7] += rb.w;
        }
        float4 oa4, ob4;
        oa4.x = t[0]; oa4.y = t[1]; oa4.z = t[2]; oa4.w = t[3];
        ob4.x = t[4]; ob4.y = t[5]; ob4.z = t[6]; ob4.w = t[7];
        *(float4*)(Y + (size_t)bz * ybs + (size_t)o * ldY + nA) = oa4;
        *(float4*)(Y + (size_t)bz * ybs + (size_t)o * ldY + nB) = ob4;
    }
}

// ---------------- flash128c: stride-132 sPT, conflict-free LDS128 P reads --------
#define F_SQ 0
#define F_SK (64 * 128)
#define F_SV (F_SK + 64 * 68)
#define F_SPT (F_SV + 64 * 68)
#define F_SL (F_SPT + 64 * 132)
#define F_SMEM_FLOATS (F_SL + 128)
#define F_SMEM_BYTES (F_SMEM_FLOATS * 4)

__global__ void __launch_bounds__(256, 2) flash128_kernel() {
    extern __shared__ float sm[];
    float* sQ = sm + F_SQ;
    float* sK = sm + F_SK;
    float* sV = sm + F_SV;
    float* sPT = sm + F_SPT;    // [64][132] m rows, n cols (rows 16B-aligned)
    float* sL = sm + F_SL;

    const int tid = threadIdx.x;
    const int tx = tid & 15, ty = tid >> 4;
    const int b = blockIdx.y >> 2, h = blockIdx.y & 3;
    const size_t base = ((size_t)b * C_ + h * D_) * (size_t)N_;
    const float* qg = g_q + base + blockIdx.x * 128;
    const float* kg = g_k + base;
    const float* vg = g_v + base;
    float* og = g_attn + base + blockIdx.x * 128;

    ExpC E;
    E.c5 = pack2(1.3333558e-3f); E.c4 = pack2(9.6181291e-3f);
    E.c3 = pack2(5.5504109e-2f); E.c2 = pack2(2.4022651e-1f);
    E.c1 = pack2(6.9314718e-1f); E.c0 = pack2(1.0f);
    E.mag = pack2(12582912.0f);  E.nmag = pack2(-12582912.0f);

#pragma unroll
    for (int l = 0; l < 8; l++) {
        const int idx = tid + l * 256;
        const int r = idx >> 5, c4 = idx & 31;
        *(float4*)&sQ[r * 128 + c4 * 4] = *(const float4*)(qg + (size_t)r * N_ + c4 * 4);
    }

    ull oa2[4][4];
    ull lsum2[8];
#pragma unroll
    for (int a = 0; a < 4; a++)
#pragma unroll
        for (int j = 0; j < 4; j++) oa2[a][j] = 0ull;
#pragma unroll
    for (int i = 0; i < 8; i++) lsum2[i] = 0ull;
    __syncthreads();

    const int stag = tx >> 2;

    for (int mt = 0; mt < M_; mt += 64) {
#pragma unroll
        for (int l = 0; l < 4; l++) {
            const int idx = tid + l * 256;
            const int r = idx >> 4, c = (idx & 15) << 2;
            *(float4*)&sK[r * 68 + c] = *(const float4*)(kg + (size_t)r * M_ + mt + c);
            *(float4*)&sV[r * 68 + c] = *(const float4*)(vg + (size_t)r * M_ + mt + c);
        }
        __syncthreads();

        ull s2[16];
#pragma unroll
        for (int i = 0; i < 16; i++) s2[i] = 0ull;
#pragma unroll 4
        for (int d = 0; d < 64; d++) {
            const double2 kd = *(const double2*)&sK[d * 68 + (tx << 2)];
            const ull k0 = d2u(kd.x), k1 = d2u(kd.y);
            const float4 qa = *(const float4*)&sQ[d * 128 + (ty << 2)];
            const float4 qb = *(const float4*)&sQ[d * 128 + 64 + (ty << 2)];
            const float qf[8] = {qa.x, qa.y, qa.z, qa.w, qb.x, qb.y, qb.z, qb.w};
#pragma unroll
            for (int i = 0; i < 8; i++) {
                const ull qp = pack2(qf[i]);
                s2[i * 2 + 0] = ffma2(qp, k0, s2[i * 2 + 0]);
                s2[i * 2 + 1] = ffma2(qp, k1, s2[i * 2 + 1]);
            }
        }

#pragma unroll
        for (int i = 0; i < 8; i++) {
            const ull p0 = exp2pk(s2[i * 2 + 0], E);
            const ull p1 = exp2pk(s2[i * 2 + 1], E);
            lsum2[i] = fadd2(lsum2[i], fadd2(p0, p1));
            float pf[4];
            unpack2(p0, pf[0], pf[1]);
            unpack2(p1, pf[2], pf[3]);
            const int n = (i >> 2) * 64 + (ty << 2) + (i & 3);
#pragma unroll
            for (int jl = 0; jl < 4; jl++) {
                const int jj = (jl + stag) & 3;
                sPT[(4 * tx + jj) * 132 + n] = pf[jj];
            }
        }
        __syncthreads();

#pragma unroll 2
        for (int mb = 0; mb < 64; mb += 4) {
            float4 vv4[4];
#pragma unroll
            for (int a = 0; a < 4; a++)
                vv4[a] = *(const float4*)&sV[((ty << 2) + a) * 68 + mb];
            const float* vvf = (const float*)vv4;
#pragma unroll
            for (int mm = 0; mm < 4; mm++) {
                const float* ptrow = &sPT[(mb + mm) * 132];
                const ulonglong2 pA = *(const ulonglong2*)&ptrow[(tx << 2)];
                const ulonglong2 pB = *(const ulonglong2*)&ptrow[64 + (tx << 2)];
#pragma unroll
                for (int a = 0; a < 4; a++) {
                    const ull vb = pack2(vvf[a * 4 + mm]);
                    oa2[a][0] = ffma2(vb, pA.x, oa2[a][0]);
                    oa2[a][1] = ffma2(vb, pA.y, oa2[a][1]);
                    oa2[a][2] = ffma2(vb, pB.x, oa2[a][2]);
                    oa2[a][3] = ffma2(vb, pB.y, oa2[a][3]);
                }
            }
        }
        __syncthreads();
    }

#pragma unroll
    for (int i = 0; i < 8; i++) {
        float lo, hi;
        unpack2(lsum2[i], lo, hi);
        float l = lo + hi;
        l += __shfl_xor_sync(0xffffffffu, l, 1);
        l += __shfl_xor_sync(0xffffffffu, l, 2);
        l += __shfl_xor_sync(0xffffffffu, l, 4);
        l += __shfl_xor_sync(0xffffffffu, l, 8);
        if (tx == 0) sL[(i >> 2) * 64 + (ty << 2) + (i & 3)] = l;
    }
    __syncthreads();
    float li[8];
#pragma unroll
    for (int j = 0; j < 4; j++) {
        li[j] = 1.0f / sL[(tx << 2) + j];
        li[4 + j] = 1.0f / sL[64 + (tx << 2) + j];
    }
#pragma unroll
    for (int a = 0; a < 4; a++) {
        const int dd = (ty << 2) + a;
        float t[8];
        unpack2(oa2[a][0], t[0], t[1]);
        unpack2(oa2[a][1], t[2], t[3]);
        unpack2(oa2[a][2], t[4], t[5]);
        unpack2(oa2[a][3], t[6], t[7]);
        float4 o4a, o4b;
        o4a.x = t[0] * li[0]; o4a.y = t[1] * li[1];
        o4a.z = t[2] * li[2]; o4a.w = t[3] * li[3];
        o4b.x = t[4] * li[4]; o4b.y = t[5] * li[5];
        o4b.z = t[6] * li[6]; o4b.w = t[7] * li[7];
        *(float4*)(og + (size_t)dd * N_ + (tx << 2)) = o4a;
        *(float4*)(og + (size_t)dd * N_ + 64 + (tx << 2)) = o4b;
    }
}

// ---------------- launcher -------------------------------------------------------
extern "C" void kernel_launch(void* const* d_in, const int* in_sizes, int n_in,
                              void* d_out, int out_size) {
    const float* desc1 = (const float*)d_in[0];
    const float* desc2 = (const float*)d_in[1];
    const float* weight_v = (const float*)d_in[2];
    const float* Wq = (const float*)d_in[3];
    const float* bq = (const float*)d_in[4];
    const float* Wk = (const float*)d_in[5];
    const float* bk = (const float*)d_in[6];
    const float* Wv = (const float*)d_in[7];
    const float* bv = (const float*)d_in[8];
    const float* Wm = (const float*)d_in[9];
    const float* bm = (const float*)d_in[10];
    const float* Wc1 = (const float*)d_in[11];
    const float* bc1 = (const float*)d_in[12];
    const float* gamma = (const float*)d_in[13];
    const float* beta  = (const float*)d_in[14];
    const float* mean  = (const float*)d_in[15];
    const float* var   = (const float*)d_in[16];
    const float* Wc2 = (const float*)d_in[17];
    const float* bc2 = (const float*)d_in[18];
    float* out = (float*)d_out;

    float *q, *k, *v, *attn, *h, *bias1, *inv, *wcomb;
    cudaGetSymbolAddress((void**)&q, g_q);
    cudaGetSymbolAddress((void**)&k, g_k);
    cudaGetSymbolAddress((void**)&v, g_v);
    cudaGetSymbolAddress((void**)&attn, g_attn);
    cudaGetSymbolAddress((void**)&h, g_h);
    cudaGetSymbolAddress((void**)&bias1, g_bias1);
    cudaGetSymbolAddress((void**)&inv, g_inv);
    cudaGetSymbolAddress((void**)&wcomb, g_Wcomb);

    cudaFuncSetAttribute(flash128_kernel, cudaFuncAttributeMaxDynamicSharedMemorySize, F_SMEM_BYTES);

    const long long PB = (long long)C_ * N_;
    const long long PB2 = (long long)2 * C_ * N_;

    const float QSCALE = 0.125f * 1.4426950408889634f;

    // weight preprocessing: bias1 (BN + Wc1b@bm), Wcomb = [Wc1a | Wc1b@Wm]
    fold_kernel<<<2, 256>>>(Wc1, bc1, bm, gamma, beta, mean, var);
    combcopy_kernel<<<512, 256>>>(Wc1);
    wfold_kernel<<<dim3(4, 8), 256>>>(Wc1, Wm);

    // fused q,k,v projections
    qkv_gemm<<<dim3(N_ / 128, 6, B_), 256>>>(desc1, desc2, Wq, bq, Wk, bk, Wv, bv,
                                             weight_v, q, k, v, QSCALE);
    // attention
    flash128_kernel<<<dim3(N_ / 128, B_ * 4), 256, F_SMEM_BYTES>>>();
    // h = relu( inv * (Wcomb @ [desc1; attn]) + bias1 )
    gemm4<<<dim3(16, 4, B_), 256>>>(wcomb, 2 * C_, desc1, PB, attn, PB, C_, 2 * C_, N_,
                                    h, PB2, N_, bias1, inv, nullptr, 0, 1.0f, 1);
    // out = Wc2@h + bc2 + desc1
    gemm4<<<dim3(16, 2, B_), 256>>>(Wc2, 2 * C_, h, PB2, h, PB2, 2 * C_, 2 * C_, N_,
                                    out, PB, N_, bc2, nullptr, desc1, PB, 1.0f, 0);
}